// round 16
// baseline (speedup 1.0000x reference)
#include <cuda_runtime.h>
#include <cuda_bf16.h>
#include <math.h>
#include <cstdint>

// ---------------------------------------------------------------------------
// Problem constants
// ---------------------------------------------------------------------------
#define B_   8
#define NQ_  1024
#define C_   256
#define H_   8
#define L_   3
#define P_   8
#define FF_  1024
#define S_   21504
#define M_ROWS (B_ * NQ_)        // 8192
#define MV_ROWS (B_ * S_)        // 172032

// ---------------------------------------------------------------------------
// Scratch (static device globals)
// ---------------------------------------------------------------------------
__device__ __nv_bfloat16 g_q1b [M_ROWS * C_];
__device__ __nv_bfloat16 g_qkvb[M_ROWS * 3 * C_];
__device__ __nv_bfloat16 g_aob [M_ROWS * C_];
__device__ float         g_tgt1[M_ROWS * C_];
__device__ __nv_bfloat16 g_q2b [M_ROWS * C_];
__device__ __nv_bfloat16 g_valb[(size_t)MV_ROWS * C_];
__device__ float         g_ref [M_ROWS * 2];
__device__ float         g_off [M_ROWS * 384];
__device__ float         g_awl [M_ROWS * 192];
__device__ __nv_bfloat16 g_sampb[M_ROWS * C_];
__device__ float         g_tgt2[M_ROWS * C_];
__device__ __nv_bfloat16 g_q3b [M_ROWS * C_];
__device__ __nv_bfloat16 g_ffhb[M_ROWS * FF_];
// bf16 weights
__device__ __nv_bfloat16 g_w_qkv[768 * C_];
__device__ __nv_bfloat16 g_w_ao [C_ * C_];
__device__ __nv_bfloat16 g_w_vp [C_ * C_];
__device__ __nv_bfloat16 g_w_op [C_ * C_];
__device__ __nv_bfloat16 g_w_soaw[640 * C_];   // so(384) ++ aw(192) ++ ref(2) ++ pad
__device__ float         g_b_soaw[640];
__device__ __nv_bfloat16 g_w_l1 [FF_ * C_];
__device__ __nv_bfloat16 g_w_l2 [C_ * FF_];

// ---------------------------------------------------------------------------
// Side stream + events (load-time init; no device allocation)
// ---------------------------------------------------------------------------
static cudaStream_t g_s2 = nullptr;
static cudaEvent_t  g_evF = nullptr, g_evJ = nullptr;
static struct StreamInit {
    StreamInit() {
        cudaStreamCreateWithFlags(&g_s2, cudaStreamNonBlocking);
        cudaEventCreateWithFlags(&g_evF, cudaEventDisableTiming);
        cudaEventCreateWithFlags(&g_evJ, cudaEventDisableTiming);
    }
} g_streamInit;

// ---------------------------------------------------------------------------
// Helpers
// ---------------------------------------------------------------------------
__device__ __forceinline__ uint32_t smem_u32(const void* p) {
    uint32_t a;
    asm("{ .reg .u64 t; cvta.to.shared.u64 t, %1; cvt.u32.u64 %0, t; }"
        : "=r"(a) : "l"(p));
    return a;
}

__device__ __forceinline__ void ldsm4(uint32_t a, uint32_t& r0, uint32_t& r1,
                                      uint32_t& r2, uint32_t& r3) {
    asm volatile("ldmatrix.sync.aligned.m8n8.x4.shared.b16 {%0,%1,%2,%3}, [%4];"
                 : "=r"(r0), "=r"(r1), "=r"(r2), "=r"(r3) : "r"(a));
}

__device__ __forceinline__ void ldsm4t(uint32_t a, uint32_t& r0, uint32_t& r1,
                                       uint32_t& r2, uint32_t& r3) {
    asm volatile("ldmatrix.sync.aligned.m8n8.x4.trans.shared.b16 {%0,%1,%2,%3}, [%4];"
                 : "=r"(r0), "=r"(r1), "=r"(r2), "=r"(r3) : "r"(a));
}

__device__ __forceinline__ void mma16816(float* c, const uint32_t* a, const uint32_t* b) {
    asm volatile(
        "mma.sync.aligned.m16n8k16.row.col.f32.bf16.bf16.f32 "
        "{%0,%1,%2,%3}, {%4,%5,%6,%7}, {%8,%9}, {%0,%1,%2,%3};"
        : "+f"(c[0]), "+f"(c[1]), "+f"(c[2]), "+f"(c[3])
        : "r"(a[0]), "r"(a[1]), "r"(a[2]), "r"(a[3]), "r"(b[0]), "r"(b[1]));
}

__device__ __forceinline__ float gelu_f(float v) {
    return 0.5f * v * (1.0f + erff(v * 0.70710678118654752f));
}

// ---------------------------------------------------------------------------
// vp-only conversion (runs first on side stream; 16384 float4 units)
// ---------------------------------------------------------------------------
__global__ __launch_bounds__(256) void cvt_vp_kernel(
    const float* __restrict__ w_vp, __nv_bfloat16* __restrict__ o_vp)
{
    int i = blockIdx.x * 256 + threadIdx.x;
    if (i >= 16384) return;
    float4 v = ((const float4*)w_vp)[i];
    __nv_bfloat162* yo = (__nv_bfloat162*)o_vp;
    yo[2 * i]     = __floats2bfloat162_rn(v.x, v.y);
    yo[2 * i + 1] = __floats2bfloat162_rn(v.z, v.w);
}

// ---------------------------------------------------------------------------
// Fused weight conversion for everything EXCEPT vp (4-elem units).
// ---------------------------------------------------------------------------
#define CVT_TOTAL4 254112
__global__ __launch_bounds__(256) void cvt_weights_kernel(
    const float* __restrict__ w_qkv, const float* __restrict__ w_ao,
    const float* __restrict__ w_op,
    const float* __restrict__ w_so,  const float* __restrict__ w_aw,
    const float* __restrict__ w_ref, const float* __restrict__ ref_b,
    const float* __restrict__ w_l1,  const float* __restrict__ w_l2,
    const float* __restrict__ so_b,  const float* __restrict__ aw_b,
    __nv_bfloat16* __restrict__ o_qkv, __nv_bfloat16* __restrict__ o_ao,
    __nv_bfloat16* __restrict__ o_op,
    __nv_bfloat16* __restrict__ o_soaw, float* __restrict__ o_bsoaw,
    __nv_bfloat16* __restrict__ o_l1,  __nv_bfloat16* __restrict__ o_l2)
{
    int i = blockIdx.x * 256 + threadIdx.x;
    if (i >= CVT_TOTAL4) return;
    if (i >= 253952) {
        int j = i - 253952;
        float4 v;
        float* vv = (float*)&v;
        #pragma unroll
        for (int t = 0; t < 4; t++) {
            int e = 4 * j + t;
            float bv = 0.f;
            if (e < 384)      bv = so_b[e];
            else if (e < 576) bv = aw_b[e - 384];
            else if (e < 578) bv = ref_b[e - 576];
            vv[t] = bv;
        }
        ((float4*)o_bsoaw)[j] = v;
        return;
    }
    const float* src; __nv_bfloat16* dst; int j; int joff = 0; bool zero = false;
    if      (i < 49152)  { src = w_qkv; dst = o_qkv; j = i; }
    else if (i < 65536)  { src = w_ao;  dst = o_ao;  j = i - 49152; }
    else if (i < 81920)  { src = w_op;  dst = o_op;  j = i - 65536; }
    else if (i < 122880) {
        dst = o_soaw; j = i - 81920;
        if (j < 24576)      { src = w_so; }
        else if (j < 36864) { src = w_aw;  joff = 24576; }
        else if (j < 36992) { src = w_ref; joff = 36864; }
        else                { src = w_so;  zero = true; }
    }
    else if (i < 188416) { src = w_l1;  dst = o_l1;  j = i - 122880; }
    else                 { src = w_l2;  dst = o_l2;  j = i - 188416; }
    __nv_bfloat162* yo = (__nv_bfloat162*)dst;
    if (zero) {
        __nv_bfloat162 z = __floats2bfloat162_rn(0.f, 0.f);
        yo[2 * j] = z;
        yo[2 * j + 1] = z;
    } else {
        float4 v = ((const float4*)src)[j - joff];
        yo[2 * j]     = __floats2bfloat162_rn(v.x, v.y);
        yo[2 * j + 1] = __floats2bfloat162_rn(v.z, v.w);
    }
}

// ---------------------------------------------------------------------------
// LayerNorm: warp-per-row (8 rows per 256-thread CTA), pure shfl reduction.
// ---------------------------------------------------------------------------
__global__ __launch_bounds__(256) void layernorm_kernel(
    const float* __restrict__ x, const float* __restrict__ w,
    const float* __restrict__ b, __nv_bfloat16* __restrict__ y)
{
    int row = blockIdx.x * 8 + (threadIdx.x >> 5);
    int lane = threadIdx.x & 31;
    const float* xr = x + (size_t)row * C_ + lane * 8;
    float4 v0 = *(const float4*)xr;
    float4 v1 = *(const float4*)(xr + 4);
    float vals[8] = {v0.x, v0.y, v0.z, v0.w, v1.x, v1.y, v1.z, v1.w};

    float s = 0.f;
    #pragma unroll
    for (int t = 0; t < 8; t++) s += vals[t];
    #pragma unroll
    for (int o = 16; o > 0; o >>= 1) s += __shfl_xor_sync(0xFFFFFFFFu, s, o);
    float mean = s * (1.0f / C_);

    float sq = 0.f;
    #pragma unroll
    for (int t = 0; t < 8; t++) {
        float d = vals[t] - mean;
        vals[t] = d;
        sq += d * d;
    }
    #pragma unroll
    for (int o = 16; o > 0; o >>= 1) sq += __shfl_xor_sync(0xFFFFFFFFu, sq, o);
    float r = rsqrtf(sq * (1.0f / C_) + 1e-5f);

    int c = lane * 8;
    float4 w0 = *(const float4*)(w + c);
    float4 w1 = *(const float4*)(w + c + 4);
    float4 b0 = *(const float4*)(b + c);
    float4 b1 = *(const float4*)(b + c + 4);
    float wv[8] = {w0.x, w0.y, w0.z, w0.w, w1.x, w1.y, w1.z, w1.w};
    float bv[8] = {b0.x, b0.y, b0.z, b0.w, b1.x, b1.y, b1.z, b1.w};
    uint32_t pk[4];
    #pragma unroll
    for (int t = 0; t < 4; t++) {
        float o0 = vals[2 * t]     * r * wv[2 * t]     + bv[2 * t];
        float o1 = vals[2 * t + 1] * r * wv[2 * t + 1] + bv[2 * t + 1];
        __nv_bfloat162 h = __floats2bfloat162_rn(o0, o1);
        pk[t] = *(uint32_t*)&h;
    }
    *(uint4*)(y + (size_t)row * C_ + c) = make_uint4(pk[0], pk[1], pk[2], pk[3]);
}

// ---------------------------------------------------------------------------
// mma.sync bf16 GEMM, BM=128/BN=128, BK=64 double-buffered (round-10 proven).
// EPI: 0=bias->bf16, 2=bias+gelu->bf16,
//      4=split: cols[0,384)->off(Yv), [384,576)->awl(res),
//               cols 576/577 -> sigmoid -> g_ref, rest dropped
// ---------------------------------------------------------------------------
#define GROW 144
#define GBUF (128 * GROW)            // 18432 per buffer
#define GEMM_SMEM (4 * GBUF)         // 73728 total

template <int EPI>
__global__ __launch_bounds__(256, 2) void mmagemm_kernel(
    const __nv_bfloat16* __restrict__ X, const __nv_bfloat16* __restrict__ W,
    const float* __restrict__ bias, const float* __restrict__ res,
    void* __restrict__ Yv, int M, int N, int K)
{
    extern __shared__ __align__(16) uint8_t smem[];

    int tid = threadIdx.x, lane = tid & 31, wid = tid >> 5;
    int bm = blockIdx.y * 128, bn = blockIdx.x * 128;
    int wm = (wid >> 2) * 64, wn = (wid & 3) * 32;
    uint32_t aBase = smem_u32(smem);
    uint32_t bBase = aBase + 2 * GBUF;

    float acc[4][4][4] = {};
    const int nch = K >> 6;

    auto loadA = [&](int ch, int buf) {
        int k0 = ch << 6;
        #pragma unroll
        for (int t = 0; t < 4; t++) {
            int idx = t * 256 + tid;
            int row = idx >> 3, seg = idx & 7;
            const void* g = X + (size_t)(bm + row) * K + k0 + seg * 8;
            uint32_t d = aBase + buf * GBUF + row * GROW + seg * 16;
            asm volatile("cp.async.ca.shared.global [%0], [%1], 16;" :: "r"(d), "l"(g));
        }
    };
    auto loadB = [&](int ch, int buf) {
        int k0 = ch << 6;
        #pragma unroll
        for (int t = 0; t < 4; t++) {
            int idx = t * 256 + tid;
            int row = idx >> 3, seg = idx & 7;
            const void* g = W + (size_t)(bn + row) * K + k0 + seg * 8;
            uint32_t d = bBase + buf * GBUF + row * GROW + seg * 16;
            asm volatile("cp.async.ca.shared.global [%0], [%1], 16;" :: "r"(d), "l"(g));
        }
    };

    loadA(0, 0);
    loadB(0, 0);
    asm volatile("cp.async.commit_group;" ::: "memory");

    for (int ch = 0; ch < nch; ch++) {
        int buf = ch & 1;
        if (ch + 1 < nch) {
            loadA(ch + 1, buf ^ 1);
            loadB(ch + 1, buf ^ 1);
            asm volatile("cp.async.commit_group;" ::: "memory");
            asm volatile("cp.async.wait_group 1;" ::: "memory");
        } else {
            asm volatile("cp.async.wait_group 0;" ::: "memory");
        }
        __syncthreads();

        #pragma unroll
        for (int kk = 0; kk < 4; kk++) {
            uint32_t a[4][4];
            #pragma unroll
            for (int mi = 0; mi < 4; mi++) {
                int row = wm + mi * 16 + (lane & 15);
                int col = kk * 16 + ((lane >> 4) << 3);
                uint32_t ad = aBase + buf * GBUF + row * GROW + col * 2;
                ldsm4(ad, a[mi][0], a[mi][1], a[mi][2], a[mi][3]);
            }
            uint32_t b[4][2];
            #pragma unroll
            for (int ng = 0; ng < 2; ng++) {
                int mm = lane >> 3;
                int row = wn + ng * 16 + (mm >> 1) * 8 + (lane & 7);
                int col = kk * 16 + (mm & 1) * 8;
                uint32_t bd = bBase + buf * GBUF + row * GROW + col * 2;
                uint32_t r0, r1, r2, r3;
                ldsm4(bd, r0, r1, r2, r3);
                b[ng * 2][0] = r0; b[ng * 2][1] = r1;
                b[ng * 2 + 1][0] = r2; b[ng * 2 + 1][1] = r3;
            }
            #pragma unroll
            for (int mi = 0; mi < 4; mi++)
                #pragma unroll
                for (int nj = 0; nj < 4; nj++)
                    mma16816(acc[mi][nj], a[mi], b[nj]);
        }
        __syncthreads();
    }

    #pragma unroll
    for (int mi = 0; mi < 4; mi++) {
        int r0 = bm + wm + mi * 16 + (lane >> 2);
        int r1 = r0 + 8;
        #pragma unroll
        for (int nj = 0; nj < 4; nj++) {
            int cb = bn + wn + nj * 8 + (lane & 3) * 2;
            if (cb >= N) continue;
            float* c = acc[mi][nj];
            float b0 = bias[cb], b1 = bias[cb + 1];
            float v00 = c[0] + b0, v01 = c[1] + b1;
            float v10 = c[2] + b0, v11 = c[3] + b1;
            if (EPI == 2) {
                v00 = gelu_f(v00); v01 = gelu_f(v01);
                v10 = gelu_f(v10); v11 = gelu_f(v11);
            }
            if (EPI == 0 || EPI == 2) {
                __nv_bfloat16* Y = (__nv_bfloat16*)Yv;
                *(__nv_bfloat162*)(Y + (size_t)r0 * N + cb) = __floats2bfloat162_rn(v00, v01);
                *(__nv_bfloat162*)(Y + (size_t)r1 * N + cb) = __floats2bfloat162_rn(v10, v11);
            } else if (EPI == 4) {
                if (cb < 384) {
                    float* OFF = (float*)Yv;
                    *(float2*)(OFF + (size_t)r0 * 384 + cb) = make_float2(v00, v01);
                    *(float2*)(OFF + (size_t)r1 * 384 + cb) = make_float2(v10, v11);
                } else if (cb < 576) {
                    float* AWL = (float*)res;
                    *(float2*)(AWL + (size_t)r0 * 192 + cb - 384) = make_float2(v00, v01);
                    *(float2*)(AWL + (size_t)r1 * 192 + cb - 384) = make_float2(v10, v11);
                } else if (cb == 576) {
                    g_ref[(size_t)r0 * 2 + 0] = 1.0f / (1.0f + expf(-v00));
                    g_ref[(size_t)r0 * 2 + 1] = 1.0f / (1.0f + expf(-v01));
                    g_ref[(size_t)r1 * 2 + 0] = 1.0f / (1.0f + expf(-v10));
                    g_ref[(size_t)r1 * 2 + 1] = 1.0f / (1.0f + expf(-v11));
                }
            }
        }
    }
}

// ---------------------------------------------------------------------------
// Small-M GEMM: BM=64/BN=128, BK=64 double-buffered, warp tile 32x32,
// up to 4 CTAs/SM (55.3KB smem). Used for the N=256 residual GEMMs
// (ao-proj, op-proj, FFN-l2): doubles the grid to 256 CTAs (fills 148 SMs)
// and improves per-SM latency hiding. EPI fixed: bias + residual -> fp32.
// ---------------------------------------------------------------------------
#define G64A (64 * GROW)             // 9216 per A buffer
#define G64B (128 * GROW)            // 18432 per B buffer
#define GEMM64_SMEM (2 * G64A + 2 * G64B)   // 55296

__global__ __launch_bounds__(256, 4) void mmagemm64_kernel(
    const __nv_bfloat16* __restrict__ X, const __nv_bfloat16* __restrict__ W,
    const float* __restrict__ bias, const float* __restrict__ res,
    float* __restrict__ Y, int M, int N, int K)
{
    extern __shared__ __align__(16) uint8_t smem[];

    int tid = threadIdx.x, lane = tid & 31, wid = tid >> 5;
    int bm = blockIdx.y * 64, bn = blockIdx.x * 128;
    int wm = (wid >> 2) * 32, wn = (wid & 3) * 32;
    uint32_t aBase = smem_u32(smem);
    uint32_t bBase = aBase + 2 * G64A;

    float acc[2][4][4] = {};
    const int nch = K >> 6;

    auto loadA = [&](int ch, int buf) {
        int k0 = ch << 6;
        #pragma unroll
        for (int t = 0; t < 2; t++) {
            int idx = t * 256 + tid;
            int row = idx >> 3, seg = idx & 7;
            const void* g = X + (size_t)(bm + row) * K + k0 + seg * 8;
            uint32_t d = aBase + buf * G64A + row * GROW + seg * 16;
            asm volatile("cp.async.ca.shared.global [%0], [%1], 16;" :: "r"(d), "l"(g));
        }
    };
    auto loadB = [&](int ch, int buf) {
        int k0 = ch << 6;
        #pragma unroll
        for (int t = 0; t < 4; t++) {
            int idx = t * 256 + tid;
            int row = idx >> 3, seg = idx & 7;
            const void* g = W + (size_t)(bn + row) * K + k0 + seg * 8;
            uint32_t d = bBase + buf * G64B + row * GROW + seg * 16;
            asm volatile("cp.async.ca.shared.global [%0], [%1], 16;" :: "r"(d), "l"(g));
        }
    };

    loadA(0, 0);
    loadB(0, 0);
    asm volatile("cp.async.commit_group;" ::: "memory");

    for (int ch = 0; ch < nch; ch++) {
        int buf = ch & 1;
        if (ch + 1 < nch) {
            loadA(ch + 1, buf ^ 1);
            loadB(ch + 1, buf ^ 1);
            asm volatile("cp.async.commit_group;" ::: "memory");
            asm volatile("cp.async.wait_group 1;" ::: "memory");
        } else {
            asm volatile("cp.async.wait_group 0;" ::: "memory");
        }
        __syncthreads();

        #pragma unroll
        for (int kk = 0; kk < 4; kk++) {
            uint32_t a[2][4];
            #pragma unroll
            for (int mi = 0; mi < 2; mi++) {
                int row = wm + mi * 16 + (lane & 15);
                int col = kk * 16 + ((lane >> 4) << 3);
                uint32_t ad = aBase + buf * G64A + row * GROW + col * 2;
                ldsm4(ad, a[mi][0], a[mi][1], a[mi][2], a[mi][3]);
            }
            uint32_t b[4][2];
            #pragma unroll
            for (int ng = 0; ng < 2; ng++) {
                int mm = lane >> 3;
                int row = wn + ng * 16 + (mm >> 1) * 8 + (lane & 7);
                int col = kk * 16 + (mm & 1) * 8;
                uint32_t bd = bBase + buf * G64B + row * GROW + col * 2;
                uint32_t r0, r1, r2, r3;
                ldsm4(bd, r0, r1, r2, r3);
                b[ng * 2][0] = r0; b[ng * 2][1] = r1;
                b[ng * 2 + 1][0] = r2; b[ng * 2 + 1][1] = r3;
            }
            #pragma unroll
            for (int mi = 0; mi < 2; mi++)
                #pragma unroll
                for (int nj = 0; nj < 4; nj++)
                    mma16816(acc[mi][nj], a[mi], b[nj]);
        }
        __syncthreads();
    }

    #pragma unroll
    for (int mi = 0; mi < 2; mi++) {
        int r0 = bm + wm + mi * 16 + (lane >> 2);
        int r1 = r0 + 8;
        #pragma unroll
        for (int nj = 0; nj < 4; nj++) {
            int cb = bn + wn + nj * 8 + (lane & 3) * 2;
            float* c = acc[mi][nj];
            float b0 = bias[cb], b1 = bias[cb + 1];
            float2 e0 = *(const float2*)(res + (size_t)r0 * N + cb);
            float2 e1 = *(const float2*)(res + (size_t)r1 * N + cb);
            *(float2*)(Y + (size_t)r0 * N + cb) =
                make_float2(c[0] + b0 + e0.x, c[1] + b1 + e0.y);
            *(float2*)(Y + (size_t)r1 * N + cb) =
                make_float2(c[2] + b0 + e1.x, c[3] + b1 + e1.y);
        }
    }
}

// ---------------------------------------------------------------------------
// Value-projection GEMM (round-10 proven): BM=64, BN=256, BK=32;
// single A buffer (register-pipelined fp32 LDG) + double B buffer. 46080 B.
// ---------------------------------------------------------------------------
#define VGROW 80
#define VA32 (64 * VGROW)            // 5120
#define VB32 (256 * VGROW)           // 20480
#define VAL_SMEM (VA32 + 2 * VB32)   // 46080

__global__ __launch_bounds__(256, 2) void valgemm_kernel(
    const float* __restrict__ X, const __nv_bfloat16* __restrict__ W,
    const float* __restrict__ bias, __nv_bfloat16* __restrict__ Y)
{
    extern __shared__ __align__(16) uint8_t smem[];
    const int K = 256, N = 256, nch = 8;

    int tid = threadIdx.x, lane = tid & 31, wid = tid >> 5;
    int bm = blockIdx.x * 64;
    int wm = (wid >> 2) * 32, wn = (wid & 3) * 64;
    uint32_t aBase = smem_u32(smem);
    uint32_t bBase = aBase + VA32;

    float acc[2][8][4] = {};
    float4 ra[2];

    auto fetchA = [&](int ch) {
        int k0 = ch << 5;
        #pragma unroll
        for (int t = 0; t < 2; t++) {
            int idx = t * 256 + tid;
            int row = idx >> 3, c4 = idx & 7;
            ra[t] = *(const float4*)(X + (size_t)(bm + row) * K + k0 + c4 * 4);
        }
    };
    auto storeA = [&]() {
        #pragma unroll
        for (int t = 0; t < 2; t++) {
            int idx = t * 256 + tid;
            int row = idx >> 3, c4 = idx & 7;
            __nv_bfloat162 h0 = __floats2bfloat162_rn(ra[t].x, ra[t].y);
            __nv_bfloat162 h1 = __floats2bfloat162_rn(ra[t].z, ra[t].w);
            uint32_t u0 = *(uint32_t*)&h0, u1 = *(uint32_t*)&h1;
            uint32_t d = aBase + row * VGROW + c4 * 8;
            asm volatile("st.shared.v2.b32 [%0], {%1,%2};" :: "r"(d), "r"(u0), "r"(u1));
        }
    };
    auto loadB = [&](int ch, int buf) {
        int k0 = ch << 5;
        #pragma unroll
        for (int t = 0; t < 4; t++) {
            int idx = t * 256 + tid;
            int row = idx >> 2, seg = idx & 3;
            const void* g = W + (size_t)row * K + k0 + seg * 8;
            uint32_t d = bBase + buf * VB32 + row * VGROW + seg * 16;
            asm volatile("cp.async.ca.shared.global [%0], [%1], 16;" :: "r"(d), "l"(g));
        }
    };

    fetchA(0);
    loadB(0, 0);
    asm volatile("cp.async.commit_group;" ::: "memory");
    storeA();
    fetchA(1);

    for (int ch = 0; ch < nch; ch++) {
        int buf = ch & 1;
        if (ch + 1 < nch) {
            loadB(ch + 1, buf ^ 1);
            asm volatile("cp.async.commit_group;" ::: "memory");
            asm volatile("cp.async.wait_group 1;" ::: "memory");
        } else {
            asm volatile("cp.async.wait_group 0;" ::: "memory");
        }
        __syncthreads();

        #pragma unroll
        for (int kk = 0; kk < 2; kk++) {
            uint32_t a[2][4];
            #pragma unroll
            for (int mi = 0; mi < 2; mi++) {
                int row = wm + mi * 16 + (lane & 15);
                int col = kk * 16 + ((lane >> 4) << 3);
                uint32_t ad = aBase + row * VGROW + col * 2;
                ldsm4(ad, a[mi][0], a[mi][1], a[mi][2], a[mi][3]);
            }
            uint32_t b[8][2];
            #pragma unroll
            for (int ng = 0; ng < 4; ng++) {
                int mm = lane >> 3;
                int row = wn + ng * 16 + (mm >> 1) * 8 + (lane & 7);
                int col = kk * 16 + (mm & 1) * 8;
                uint32_t bd = bBase + buf * VB32 + row * VGROW + col * 2;
                uint32_t r0, r1, r2, r3;
                ldsm4(bd, r0, r1, r2, r3);
                b[ng * 2][0] = r0; b[ng * 2][1] = r1;
                b[ng * 2 + 1][0] = r2; b[ng * 2 + 1][1] = r3;
            }
            #pragma unroll
            for (int mi = 0; mi < 2; mi++)
                #pragma unroll
                for (int nj = 0; nj < 8; nj++)
                    mma16816(acc[mi][nj], a[mi], b[nj]);
        }
        __syncthreads();

        if (ch + 1 < nch) {
            storeA();
            if (ch + 2 < nch) fetchA(ch + 2);
        }
    }

    #pragma unroll
    for (int mi = 0; mi < 2; mi++) {
        int r0 = bm + wm + mi * 16 + (lane >> 2);
        int r1 = r0 + 8;
        #pragma unroll
        for (int nj = 0; nj < 8; nj++) {
            int cb = wn + nj * 8 + (lane & 3) * 2;
            float* c = acc[mi][nj];
            float b0 = bias[cb], b1 = bias[cb + 1];
            *(__nv_bfloat162*)(Y + (size_t)r0 * N + cb) =
                __floats2bfloat162_rn(c[0] + b0, c[1] + b1);
            *(__nv_bfloat162*)(Y + (size_t)r1 * N + cb) =
                __floats2bfloat162_rn(c[2] + b0, c[3] + b1);
        }
    }
}

// ---------------------------------------------------------------------------
// Flash self-attention on mma.sync (base-2 online softmax, raw-score max).
// ---------------------------------------------------------------------------
__global__ __launch_bounds__(256) void attn_mma_kernel(
    const __nv_bfloat16* __restrict__ qkv, __nv_bfloat16* __restrict__ out)
{
    const float scale2 = 0.17677669529663687f * 1.4426950408889634f;
    int bh = blockIdx.y;
    int b = bh >> 3, h = bh & 7;
    int q0 = blockIdx.x * 128;
    int tid = threadIdx.x, lane = tid & 31, wid = tid >> 5;

    __shared__ __align__(16) uint8_t sQ[128 * 80];
    __shared__ __align__(16) uint8_t sK[2][64 * 80];
    __shared__ __align__(16) uint8_t sV[2][64 * 80];
    uint32_t qBase = smem_u32(sQ), kBase = smem_u32(sK), vBase = smem_u32(sV);

    #pragma unroll
    for (int t = 0; t < 2; t++) {
        int idx = t * 256 + tid;
        int row = idx >> 2, seg = idx & 3;
        const void* g = qkv + ((size_t)(b * NQ_ + q0 + row)) * 768 + h * 32 + seg * 8;
        asm volatile("cp.async.ca.shared.global [%0], [%1], 16;"
                     :: "r"(qBase + row * 80 + seg * 16), "l"(g));
    }
    auto loadKV = [&](int kb, int buf) {
        int row = tid >> 2, seg = tid & 3;
        size_t rbase = ((size_t)(b * NQ_ + kb * 64 + row)) * 768 + h * 32 + seg * 8;
        asm volatile("cp.async.ca.shared.global [%0], [%1], 16;"
                     :: "r"(kBase + buf * 5120 + row * 80 + seg * 16), "l"(qkv + rbase + 256));
        asm volatile("cp.async.ca.shared.global [%0], [%1], 16;"
                     :: "r"(vBase + buf * 5120 + row * 80 + seg * 16), "l"(qkv + rbase + 512));
    };
    loadKV(0, 0);
    asm volatile("cp.async.commit_group;" ::: "memory");
    loadKV(1, 1);
    asm volatile("cp.async.commit_group;" ::: "memory");
    asm volatile("cp.async.wait_group 1;" ::: "memory");
    __syncthreads();

    uint32_t qa[2][4];
    int wq = wid * 16;
    #pragma unroll
    for (int ks = 0; ks < 2; ks++) {
        int row = wq + (lane & 15);
        int col = ks * 16 + ((lane >> 4) << 3);
        ldsm4(qBase + row * 80 + col * 2, qa[ks][0], qa[ks][1], qa[ks][2], qa[ks][3]);
    }

    float o[4][4] = {};
    float m0 = -1e30f, m1 = -1e30f, l0 = 0.f, l1 = 0.f;
    int g8 = lane >> 3;

    for (int kb = 0; kb < 16; kb++) {
        int buf = kb & 1;

        float s[8][4] = {};
        #pragma unroll
        for (int jp = 0; jp < 4; jp++) {
            #pragma unroll
            for (int ks = 0; ks < 2; ks++) {
                int row = jp * 16 + ((g8 >> 1) << 3) + (lane & 7);
                int col = ks * 16 + ((g8 & 1) << 3);
                uint32_t r0, r1, r2, r3;
                ldsm4(kBase + buf * 5120 + row * 80 + col * 2, r0, r1, r2, r3);
                uint32_t bb0[2] = {r0, r1}, bb1[2] = {r2, r3};
                mma16816(s[jp * 2], qa[ks], bb0);
                mma16816(s[jp * 2 + 1], qa[ks], bb1);
            }
        }

        float mn0 = m0, mn1 = m1;
        #pragma unroll
        for (int j = 0; j < 8; j++) {
            mn0 = fmaxf(mn0, fmaxf(s[j][0], s[j][1]));
            mn1 = fmaxf(mn1, fmaxf(s[j][2], s[j][3]));
        }
        mn0 = fmaxf(mn0, __shfl_xor_sync(0xFFFFFFFFu, mn0, 1));
        mn0 = fmaxf(mn0, __shfl_xor_sync(0xFFFFFFFFu, mn0, 2));
        mn1 = fmaxf(mn1, __shfl_xor_sync(0xFFFFFFFFu, mn1, 1));
        mn1 = fmaxf(mn1, __shfl_xor_sync(0xFFFFFFFFu, mn1, 2));
        float c0 = exp2f((m0 - mn0) * scale2), c1 = exp2f((m1 - mn1) * scale2);
        m0 = mn0; m1 = mn1;
        float nm0 = mn0 * scale2, nm1 = mn1 * scale2;
        l0 *= c0; l1 *= c1;
        #pragma unroll
        for (int j = 0; j < 8; j++) {
            s[j][0] = exp2f(fmaf(s[j][0], scale2, -nm0));
            s[j][1] = exp2f(fmaf(s[j][1], scale2, -nm0));
            s[j][2] = exp2f(fmaf(s[j][2], scale2, -nm1));
            s[j][3] = exp2f(fmaf(s[j][3], scale2, -nm1));
            l0 += s[j][0] + s[j][1];
            l1 += s[j][2] + s[j][3];
        }

        uint32_t pa[4][4];
        #pragma unroll
        for (int kk = 0; kk < 4; kk++) {
            __nv_bfloat162 h0 = __floats2bfloat162_rn(s[2 * kk][0], s[2 * kk][1]);
            __nv_bfloat162 h1 = __floats2bfloat162_rn(s[2 * kk][2], s[2 * kk][3]);
            __nv_bfloat162 h2 = __floats2bfloat162_rn(s[2 * kk + 1][0], s[2 * kk + 1][1]);
            __nv_bfloat162 h3 = __floats2bfloat162_rn(s[2 * kk + 1][2], s[2 * kk + 1][3]);
            pa[kk][0] = *(uint32_t*)&h0; pa[kk][1] = *(uint32_t*)&h1;
            pa[kk][2] = *(uint32_t*)&h2; pa[kk][3] = *(uint32_t*)&h3;
        }

        #pragma unroll
        for (int nd = 0; nd < 4; nd++) {
            o[nd][0] *= c0; o[nd][1] *= c0; o[nd][2] *= c1; o[nd][3] *= c1;
        }

        #pragma unroll
        for (int kk = 0; kk < 4; kk++) {
            #pragma unroll
            for (int np = 0; np < 2; np++) {
                int row = kk * 16 + ((g8 & 1) << 3) + (lane & 7);
                int col = np * 16 + ((g8 >> 1) << 3);
                uint32_t r0, r1, r2, r3;
                ldsm4t(vBase + buf * 5120 + row * 80 + col * 2, r0, r1, r2, r3);
                uint32_t bb0[2] = {r0, r1}, bb1[2] = {r2, r3};
                mma16816(o[np * 2], pa[kk], bb0);
                mma16816(o[np * 2 + 1], pa[kk], bb1);
            }
        }

        __syncthreads();
        if (kb + 2 < 16) {
            loadKV(kb + 2, buf);
            asm volatile("cp.async.commit_group;" ::: "memory");
            asm volatile("cp.async.wait_group 1;" ::: "memory");
            __syncthreads();
        } else if (kb + 1 < 16) {
            asm volatile("cp.async.wait_group 0;" ::: "memory");
            __syncthreads();
        }
    }

    l0 += __shfl_xor_sync(0xFFFFFFFFu, l0, 1);
    l0 += __shfl_xor_sync(0xFFFFFFFFu, l0, 2);
    l1 += __shfl_xor_sync(0xFFFFFFFFu, l1, 1);
    l1 += __shfl_xor_sync(0xFFFFFFFFu, l1, 2);

    float inv0 = 1.f / l0, inv1 = 1.f / l1;
    int r = lane >> 2;
    int cb = (lane & 3) * 2;
    size_t mr0 = (size_t)(b * NQ_ + q0 + wq + r);
    size_t mr1 = mr0 + 8;
    #pragma unroll
    for (int nd = 0; nd < 4; nd++) {
        int col = h * 32 + nd * 8 + cb;
        *(__nv_bfloat162*)(out + mr0 * C_ + col) =
            __floats2bfloat162_rn(o[nd][0] * inv0, o[nd][1] * inv0);
        *(__nv_bfloat162*)(out + mr1 * C_ + col) =
            __floats2bfloat162_rn(o[nd][2] * inv1, o[nd][3] * inv1);
    }
}

// ---------------------------------------------------------------------------
// MS-deformable sampling (bf16 value, bf16 out)
// ---------------------------------------------------------------------------
__global__ __launch_bounds__(256) void deform_kernel(
    const __nv_bfloat16* __restrict__ value, const float* __restrict__ ref,
    const float* __restrict__ off, const float* __restrict__ awl,
    __nv_bfloat16* __restrict__ out)
{
    int gwarp = (blockIdx.x * blockDim.x + threadIdx.x) >> 5;
    int lane = threadIdx.x & 31;
    int m = gwarp >> 3;
    int h = gwarp & 7;
    int b = m >> 10;

    float logit = -1e30f;
    if (lane < 24) logit = awl[(size_t)m * 192 + h * 24 + lane];
    float mx = logit;
    #pragma unroll
    for (int o = 16; o > 0; o >>= 1) mx = fmaxf(mx, __shfl_xor_sync(0xFFFFFFFFu, mx, o));
    float e = (lane < 24) ? __expf(logit - mx) : 0.f;
    float sum = e;
    #pragma unroll
    for (int o = 16; o > 0; o >>= 1) sum += __shfl_xor_sync(0xFFFFFFFFu, sum, o);
    float inv = 1.f / sum;

    float rx = ref[(size_t)m * 2 + 0];
    float ry = ref[(size_t)m * 2 + 1];

    const int HL[3] = {128, 64, 32};
    const int WL[3] = {128, 64, 32};
    const int ST[3] = {0, 16384, 20480};

    float acc = 0.f;
    #pragma unroll
    for (int l = 0; l < 3; l++) {
        int h_l = HL[l], w_l = WL[l];
        const __nv_bfloat16* base = value + ((size_t)b * S_ + ST[l]) * C_ + h * 32 + lane;
        float fw = (float)w_l, fh = (float)h_l;
        #pragma unroll
        for (int p = 0; p < 8; p++) {
            int j = l * 8 + p;
            float aw = __shfl_sync(0xFFFFFFFFu, e, j) * inv;
            size_t ob = (size_t)m * 384 + ((h * 3 + l) * 8 + p) * 2;
            float ox = off[ob + 0];
            float oy = off[ob + 1];
            float locx = rx + ox / fw;
            float locy = ry + oy / fh;
            float gx = locx * fw - 0.5f;
            float gy = locy * fh - 0.5f;
            float x0f = floorf(gx), y0f = floorf(gy);
            float lx = gx - x0f, ly = gy - y0f;
            int x0 = (int)x0f, y0 = (int)y0f;
            int x1 = x0 + 1, y1 = y0 + 1;
            bool vx0 = ((unsigned)x0 < (unsigned)w_l);
            bool vx1 = ((unsigned)x1 < (unsigned)w_l);
            bool vy0 = ((unsigned)y0 < (unsigned)h_l);
            bool vy1 = ((unsigned)y1 < (unsigned)h_l);
            int x0c = min(max(x0, 0), w_l - 1);
            int x1c = min(max(x1, 0), w_l - 1);
            int y0c = min(max(y0, 0), h_l - 1);
            int y1c = min(max(y1, 0), h_l - 1);
            float v00 = 0.f, v01 = 0.f, v10 = 0.f, v11 = 0.f;
            if (vy0) {
                if (vx0) v00 = __bfloat162float(base[(size_t)(y0c * w_l + x0c) * C_]);
                if (vx1) v01 = __bfloat162float(base[(size_t)(y0c * w_l + x1c) * C_]);
            }
            if (vy1) {
                if (vx0) v10 = __bfloat162float(base[(size_t)(y1c * w_l + x0c) * C_]);
                if (vx1) v11 = __bfloat162float(base[(size_t)(y1c * w_l + x1c) * C_]);
            }
            float sres = v00 * ((1.f - lx) * (1.f - ly))
                       + v01 * (lx * (1.f - ly))
                       + v10 * ((1.f - lx) * ly)
                       + v11 * (lx * ly);
            acc += aw * sres;
        }
    }
    out[(size_t)m * C_ + h * 32 + lane] = __float2bfloat16(acc);
}

// ---------------------------------------------------------------------------
// Launch
// ---------------------------------------------------------------------------
extern "C" void kernel_launch(void* const* d_in, const int* in_sizes, int n_in,
                              void* d_out, int out_size)
{
    const float* tgt        = (const float*)d_in[0];
    const float* memory     = (const float*)d_in[1];
    const float* n1_w       = (const float*)d_in[2];
    const float* n1_b       = (const float*)d_in[3];
    const float* attn_in_w  = (const float*)d_in[4];
    const float* attn_in_b  = (const float*)d_in[5];
    const float* attn_out_w = (const float*)d_in[6];
    const float* attn_out_b = (const float*)d_in[7];
    const float* n2_w       = (const float*)d_in[8];
    const float* n2_b       = (const float*)d_in[9];
    const float* ref_w      = (const float*)d_in[10];
    const float* ref_b      = (const float*)d_in[11];
    const float* so_w       = (const float*)d_in[12];
    const float* so_b       = (const float*)d_in[13];
    const float* aw_w       = (const float*)d_in[14];
    const float* aw_b       = (const float*)d_in[15];
    const float* vp_w       = (const float*)d_in[16];
    const float* vp_b       = (const float*)d_in[17];
    const float* op_w       = (const float*)d_in[18];
    const float* op_b       = (const float*)d_in[19];
    const float* n3_w       = (const float*)d_in[20];
    const float* n3_b       = (const float*)d_in[21];
    const float* l1_w       = (const float*)d_in[22];
    const float* l1_b       = (const float*)d_in[23];
    const float* l2_w       = (const float*)d_in[24];
    const float* l2_b       = (const float*)d_in[25];
    float* out = (float*)d_out;

    void* p;
    cudaGetSymbolAddress(&p, g_q1b);    __nv_bfloat16* q1    = (__nv_bfloat16*)p;
    cudaGetSymbolAddress(&p, g_qkvb);   __nv_bfloat16* qkv   = (__nv_bfloat16*)p;
    cudaGetSymbolAddress(&p, g_aob);    __nv_bfloat16* ao    = (__nv_bfloat16*)p;
    cudaGetSymbolAddress(&p, g_tgt1);   float* tgt1          = (float*)p;
    cudaGetSymbolAddress(&p, g_q2b);    __nv_bfloat16* q2    = (__nv_bfloat16*)p;
    cudaGetSymbolAddress(&p, g_valb);   __nv_bfloat16* valb  = (__nv_bfloat16*)p;
    cudaGetSymbolAddress(&p, g_ref);    float* refb          = (float*)p;
    cudaGetSymbolAddress(&p, g_off);    float* offb          = (float*)p;
    cudaGetSymbolAddress(&p, g_awl);    float* awlb          = (float*)p;
    cudaGetSymbolAddress(&p, g_sampb);  __nv_bfloat16* samp  = (__nv_bfloat16*)p;
    cudaGetSymbolAddress(&p, g_tgt2);   float* tgt2          = (float*)p;
    cudaGetSymbolAddress(&p, g_q3b);    __nv_bfloat16* q3    = (__nv_bfloat16*)p;
    cudaGetSymbolAddress(&p, g_ffhb);   __nv_bfloat16* ffh   = (__nv_bfloat16*)p;
    cudaGetSymbolAddress(&p, g_w_qkv);  __nv_bfloat16* wqkv  = (__nv_bfloat16*)p;
    cudaGetSymbolAddress(&p, g_w_ao);   __nv_bfloat16* wao   = (__nv_bfloat16*)p;
    cudaGetSymbolAddress(&p, g_w_vp);   __nv_bfloat16* wvp   = (__nv_bfloat16*)p;
    cudaGetSymbolAddress(&p, g_w_op);   __nv_bfloat16* wop   = (__nv_bfloat16*)p;
    cudaGetSymbolAddress(&p, g_w_soaw); __nv_bfloat16* wsoaw = (__nv_bfloat16*)p;
    cudaGetSymbolAddress(&p, g_b_soaw); float* bsoaw         = (float*)p;
    cudaGetSymbolAddress(&p, g_w_l1);   __nv_bfloat16* wl1   = (__nv_bfloat16*)p;
    cudaGetSymbolAddress(&p, g_w_l2);   __nv_bfloat16* wl2   = (__nv_bfloat16*)p;

    cudaFuncSetAttribute(mmagemm_kernel<0>, cudaFuncAttributeMaxDynamicSharedMemorySize, GEMM_SMEM);
    cudaFuncSetAttribute(mmagemm_kernel<2>, cudaFuncAttributeMaxDynamicSharedMemorySize, GEMM_SMEM);
    cudaFuncSetAttribute(mmagemm_kernel<4>, cudaFuncAttributeMaxDynamicSharedMemorySize, GEMM_SMEM);
    cudaFuncSetAttribute(mmagemm64_kernel,  cudaFuncAttributeMaxDynamicSharedMemorySize, GEMM64_SMEM);
    cudaFuncSetAttribute(valgemm_kernel,    cudaFuncAttributeMaxDynamicSharedMemorySize, VAL_SMEM);

    // ---- fork side stream into the capture, then vp cvt + value projection ----
    cudaEventRecord(g_evF, 0);
    cudaStreamWaitEvent(g_s2, g_evF, 0);
    cvt_vp_kernel<<<64, 256, 0, g_s2>>>(vp_w, wvp);
    valgemm_kernel<<<MV_ROWS / 64, 256, VAL_SMEM, g_s2>>>(memory, wvp, vp_b, valb);
    cudaEventRecord(g_evJ, g_s2);

    // ---- main stream: remaining weight conversions ----
    cvt_weights_kernel<<<(CVT_TOTAL4 + 255) / 256, 256>>>(
        attn_in_w, attn_out_w, op_w, so_w, aw_w, ref_w, ref_b,
        l1_w, l2_w, so_b, aw_b,
        wqkv, wao, wop, wsoaw, bsoaw, wl1, wl2);

    // ---- self-attention block ----
    layernorm_kernel<<<M_ROWS / 8, 256>>>(tgt, n1_w, n1_b, q1);
    mmagemm_kernel<0><<<dim3(6, 64), 256, GEMM_SMEM>>>(q1, wqkv, attn_in_b, nullptr,
                                                       qkv, M_ROWS, 768, C_);
    attn_mma_kernel<<<dim3(NQ_ / 128, B_ * H_), 256>>>(qkv, ao);
    mmagemm64_kernel<<<dim3(2, 128), 256, GEMM64_SMEM>>>(ao, wao, attn_out_b, tgt,
                                                         tgt1, M_ROWS, C_, C_);

    // ---- deformable cross-attention block ----
    layernorm_kernel<<<M_ROWS / 8, 256>>>(tgt1, n2_w, n2_b, q2);
    mmagemm_kernel<4><<<dim3(5, 64), 256, GEMM_SMEM>>>(q2, wsoaw, bsoaw,
                                                       awlb, offb, M_ROWS, 640, C_);
    cudaStreamWaitEvent(0, g_evJ, 0);
    deform_kernel<<<(M_ROWS * H_) / 8, 256>>>(valb, refb, offb, awlb, samp);
    mmagemm64_kernel<<<dim3(2, 128), 256, GEMM64_SMEM>>>(samp, wop, op_b, tgt1,
                                                         tgt2, M_ROWS, C_, C_);

    // ---- FFN block ----
    layernorm_kernel<<<M_ROWS / 8, 256>>>(tgt2, n3_w, n3_b, q3);
    mmagemm_kernel<2><<<dim3(8, 64), 256, GEMM_SMEM>>>(q3, wl1, l1_b, nullptr,
                                                       ffh, M_ROWS, FF_, C_);
    mmagemm64_kernel<<<dim3(2, 128), 256, GEMM64_SMEM>>>(ffh, wl2, l2_b, tgt2,
                                                         out, M_ROWS, C_, FF_);
}

// round 17
// speedup vs baseline: 1.0160x; 1.0160x over previous
#include <cuda_runtime.h>
#include <cuda_bf16.h>
#include <math.h>
#include <cstdint>

// ---------------------------------------------------------------------------
// Problem constants
// ---------------------------------------------------------------------------
#define B_   8
#define NQ_  1024
#define C_   256
#define H_   8
#define L_   3
#define P_   8
#define FF_  1024
#define S_   21504
#define M_ROWS (B_ * NQ_)        // 8192
#define MV_ROWS (B_ * S_)        // 172032

// ---------------------------------------------------------------------------
// Scratch (static device globals)
// ---------------------------------------------------------------------------
__device__ __nv_bfloat16 g_q1b [M_ROWS * C_];
__device__ __nv_bfloat16 g_qkvb[M_ROWS * 3 * C_];
__device__ __nv_bfloat16 g_aob [M_ROWS * C_];
__device__ float         g_tgt1[M_ROWS * C_];
__device__ __nv_bfloat16 g_q2b [M_ROWS * C_];
__device__ __nv_bfloat16 g_valb[(size_t)MV_ROWS * C_];
__device__ float         g_ref [M_ROWS * 2];
__device__ float         g_off [M_ROWS * 384];
__device__ float         g_awl [M_ROWS * 192];
__device__ __nv_bfloat16 g_sampb[M_ROWS * C_];
__device__ float         g_tgt2[M_ROWS * C_];
__device__ __nv_bfloat16 g_q3b [M_ROWS * C_];
__device__ __nv_bfloat16 g_ffhb[M_ROWS * FF_];
// bf16 weights
__device__ __nv_bfloat16 g_w_qkv[768 * C_];
__device__ __nv_bfloat16 g_w_ao [C_ * C_];
__device__ __nv_bfloat16 g_w_vp [C_ * C_];
__device__ __nv_bfloat16 g_w_op [C_ * C_];
__device__ __nv_bfloat16 g_w_soaw[640 * C_];   // so(384) ++ aw(192) ++ ref(2) ++ pad
__device__ float         g_b_soaw[640];
__device__ __nv_bfloat16 g_w_l1 [FF_ * C_];
__device__ __nv_bfloat16 g_w_l2 [C_ * FF_];

// ---------------------------------------------------------------------------
// Side stream + events (load-time init; no device allocation)
// ---------------------------------------------------------------------------
static cudaStream_t g_s2 = nullptr;
static cudaEvent_t  g_evF = nullptr, g_evJ = nullptr;
static struct StreamInit {
    StreamInit() {
        cudaStreamCreateWithFlags(&g_s2, cudaStreamNonBlocking);
        cudaEventCreateWithFlags(&g_evF, cudaEventDisableTiming);
        cudaEventCreateWithFlags(&g_evJ, cudaEventDisableTiming);
    }
} g_streamInit;

// ---------------------------------------------------------------------------
// Helpers
// ---------------------------------------------------------------------------
__device__ __forceinline__ uint32_t smem_u32(const void* p) {
    uint32_t a;
    asm("{ .reg .u64 t; cvta.to.shared.u64 t, %1; cvt.u32.u64 %0, t; }"
        : "=r"(a) : "l"(p));
    return a;
}

__device__ __forceinline__ void ldsm4(uint32_t a, uint32_t& r0, uint32_t& r1,
                                      uint32_t& r2, uint32_t& r3) {
    asm volatile("ldmatrix.sync.aligned.m8n8.x4.shared.b16 {%0,%1,%2,%3}, [%4];"
                 : "=r"(r0), "=r"(r1), "=r"(r2), "=r"(r3) : "r"(a));
}

__device__ __forceinline__ void ldsm4t(uint32_t a, uint32_t& r0, uint32_t& r1,
                                       uint32_t& r2, uint32_t& r3) {
    asm volatile("ldmatrix.sync.aligned.m8n8.x4.trans.shared.b16 {%0,%1,%2,%3}, [%4];"
                 : "=r"(r0), "=r"(r1), "=r"(r2), "=r"(r3) : "r"(a));
}

__device__ __forceinline__ void mma16816(float* c, const uint32_t* a, const uint32_t* b) {
    asm volatile(
        "mma.sync.aligned.m16n8k16.row.col.f32.bf16.bf16.f32 "
        "{%0,%1,%2,%3}, {%4,%5,%6,%7}, {%8,%9}, {%0,%1,%2,%3};"
        : "+f"(c[0]), "+f"(c[1]), "+f"(c[2]), "+f"(c[3])
        : "r"(a[0]), "r"(a[1]), "r"(a[2]), "r"(a[3]), "r"(b[0]), "r"(b[1]));
}

__device__ __forceinline__ float gelu_f(float v) {
    return 0.5f * v * (1.0f + erff(v * 0.70710678118654752f));
}

// ---------------------------------------------------------------------------
// Fused weight conversion (4-elem units).
// soaw rows: [0,384) so, [384,576) aw, [576,578) ref, rest zero.
// ---------------------------------------------------------------------------
#define CVT_TOTAL4 270496
__global__ __launch_bounds__(256) void cvt_weights_kernel(
    const float* __restrict__ w_qkv, const float* __restrict__ w_ao,
    const float* __restrict__ w_vp,  const float* __restrict__ w_op,
    const float* __restrict__ w_so,  const float* __restrict__ w_aw,
    const float* __restrict__ w_ref, const float* __restrict__ ref_b,
    const float* __restrict__ w_l1,  const float* __restrict__ w_l2,
    const float* __restrict__ so_b,  const float* __restrict__ aw_b,
    __nv_bfloat16* __restrict__ o_qkv, __nv_bfloat16* __restrict__ o_ao,
    __nv_bfloat16* __restrict__ o_vp,  __nv_bfloat16* __restrict__ o_op,
    __nv_bfloat16* __restrict__ o_soaw, float* __restrict__ o_bsoaw,
    __nv_bfloat16* __restrict__ o_l1,  __nv_bfloat16* __restrict__ o_l2)
{
    int i = blockIdx.x * 256 + threadIdx.x;
    if (i >= CVT_TOTAL4) return;
    if (i >= 270336) {
        int j = i - 270336;
        float4 v;
        float* vv = (float*)&v;
        #pragma unroll
        for (int t = 0; t < 4; t++) {
            int e = 4 * j + t;
            float bv = 0.f;
            if (e < 384)      bv = so_b[e];
            else if (e < 576) bv = aw_b[e - 384];
            else if (e < 578) bv = ref_b[e - 576];
            vv[t] = bv;
        }
        ((float4*)o_bsoaw)[j] = v;
        return;
    }
    const float* src; __nv_bfloat16* dst; int j; int joff = 0; bool zero = false;
    if      (i < 49152)  { src = w_qkv; dst = o_qkv; j = i; }
    else if (i < 65536)  { src = w_ao;  dst = o_ao;  j = i - 49152; }
    else if (i < 81920)  { src = w_vp;  dst = o_vp;  j = i - 65536; }
    else if (i < 98304)  { src = w_op;  dst = o_op;  j = i - 81920; }
    else if (i < 139264) {
        dst = o_soaw; j = i - 98304;
        if (j < 24576)      { src = w_so; }
        else if (j < 36864) { src = w_aw;  joff = 24576; }
        else if (j < 36992) { src = w_ref; joff = 36864; }
        else                { src = w_so;  zero = true; }
    }
    else if (i < 204800) { src = w_l1;  dst = o_l1;  j = i - 139264; }
    else                 { src = w_l2;  dst = o_l2;  j = i - 204800; }
    __nv_bfloat162* yo = (__nv_bfloat162*)dst;
    if (zero) {
        __nv_bfloat162 z = __floats2bfloat162_rn(0.f, 0.f);
        yo[2 * j] = z;
        yo[2 * j + 1] = z;
    } else {
        float4 v = ((const float4*)src)[j - joff];
        yo[2 * j]     = __floats2bfloat162_rn(v.x, v.y);
        yo[2 * j + 1] = __floats2bfloat162_rn(v.z, v.w);
    }
}

// ---------------------------------------------------------------------------
// LayerNorm: warp-per-row (8 rows per 256-thread CTA), pure shfl reduction.
// ---------------------------------------------------------------------------
__global__ __launch_bounds__(256) void layernorm_kernel(
    const float* __restrict__ x, const float* __restrict__ w,
    const float* __restrict__ b, __nv_bfloat16* __restrict__ y)
{
    int row = blockIdx.x * 8 + (threadIdx.x >> 5);
    int lane = threadIdx.x & 31;
    const float* xr = x + (size_t)row * C_ + lane * 8;
    float4 v0 = *(const float4*)xr;
    float4 v1 = *(const float4*)(xr + 4);
    float vals[8] = {v0.x, v0.y, v0.z, v0.w, v1.x, v1.y, v1.z, v1.w};

    float s = 0.f;
    #pragma unroll
    for (int t = 0; t < 8; t++) s += vals[t];
    #pragma unroll
    for (int o = 16; o > 0; o >>= 1) s += __shfl_xor_sync(0xFFFFFFFFu, s, o);
    float mean = s * (1.0f / C_);

    float sq = 0.f;
    #pragma unroll
    for (int t = 0; t < 8; t++) {
        float d = vals[t] - mean;
        vals[t] = d;
        sq += d * d;
    }
    #pragma unroll
    for (int o = 16; o > 0; o >>= 1) sq += __shfl_xor_sync(0xFFFFFFFFu, sq, o);
    float r = rsqrtf(sq * (1.0f / C_) + 1e-5f);

    int c = lane * 8;
    float4 w0 = *(const float4*)(w + c);
    float4 w1 = *(const float4*)(w + c + 4);
    float4 b0 = *(const float4*)(b + c);
    float4 b1 = *(const float4*)(b + c + 4);
    float wv[8] = {w0.x, w0.y, w0.z, w0.w, w1.x, w1.y, w1.z, w1.w};
    float bv[8] = {b0.x, b0.y, b0.z, b0.w, b1.x, b1.y, b1.z, b1.w};
    uint32_t pk[4];
    #pragma unroll
    for (int t = 0; t < 4; t++) {
        float o0 = vals[2 * t]     * r * wv[2 * t]     + bv[2 * t];
        float o1 = vals[2 * t + 1] * r * wv[2 * t + 1] + bv[2 * t + 1];
        __nv_bfloat162 h = __floats2bfloat162_rn(o0, o1);
        pk[t] = *(uint32_t*)&h;
    }
    *(uint4*)(y + (size_t)row * C_ + c) = make_uint4(pk[0], pk[1], pk[2], pk[3]);
}

// ---------------------------------------------------------------------------
// mma.sync bf16 GEMM, BK=64 double-buffered (round-10 proven).
// EPI: 0=bias->bf16, 1=bias+res->fp32, 2=bias+gelu->bf16,
//      4=split: cols[0,384)->off(Yv), [384,576)->awl(res),
//               cols 576/577 -> sigmoid -> g_ref, rest dropped
// ---------------------------------------------------------------------------
#define GROW 144
#define GBUF (128 * GROW)            // 18432 per buffer
#define GEMM_SMEM (4 * GBUF)         // 73728 total

template <int EPI>
__global__ __launch_bounds__(256, 2) void mmagemm_kernel(
    const __nv_bfloat16* __restrict__ X, const __nv_bfloat16* __restrict__ W,
    const float* __restrict__ bias, const float* __restrict__ res,
    void* __restrict__ Yv, int M, int N, int K)
{
    extern __shared__ __align__(16) uint8_t smem[];

    int tid = threadIdx.x, lane = tid & 31, wid = tid >> 5;
    int bm = blockIdx.y * 128, bn = blockIdx.x * 128;
    int wm = (wid >> 2) * 64, wn = (wid & 3) * 32;
    uint32_t aBase = smem_u32(smem);
    uint32_t bBase = aBase + 2 * GBUF;

    float acc[4][4][4] = {};
    const int nch = K >> 6;

    auto loadA = [&](int ch, int buf) {
        int k0 = ch << 6;
        #pragma unroll
        for (int t = 0; t < 4; t++) {
            int idx = t * 256 + tid;
            int row = idx >> 3, seg = idx & 7;
            const void* g = X + (size_t)(bm + row) * K + k0 + seg * 8;
            uint32_t d = aBase + buf * GBUF + row * GROW + seg * 16;
            asm volatile("cp.async.ca.shared.global [%0], [%1], 16;" :: "r"(d), "l"(g));
        }
    };
    auto loadB = [&](int ch, int buf) {
        int k0 = ch << 6;
        #pragma unroll
        for (int t = 0; t < 4; t++) {
            int idx = t * 256 + tid;
            int row = idx >> 3, seg = idx & 7;
            const void* g = W + (size_t)(bn + row) * K + k0 + seg * 8;
            uint32_t d = bBase + buf * GBUF + row * GROW + seg * 16;
            asm volatile("cp.async.ca.shared.global [%0], [%1], 16;" :: "r"(d), "l"(g));
        }
    };

    loadA(0, 0);
    loadB(0, 0);
    asm volatile("cp.async.commit_group;" ::: "memory");

    for (int ch = 0; ch < nch; ch++) {
        int buf = ch & 1;
        if (ch + 1 < nch) {
            loadA(ch + 1, buf ^ 1);
            loadB(ch + 1, buf ^ 1);
            asm volatile("cp.async.commit_group;" ::: "memory");
            asm volatile("cp.async.wait_group 1;" ::: "memory");
        } else {
            asm volatile("cp.async.wait_group 0;" ::: "memory");
        }
        __syncthreads();

        #pragma unroll
        for (int kk = 0; kk < 4; kk++) {
            uint32_t a[4][4];
            #pragma unroll
            for (int mi = 0; mi < 4; mi++) {
                int row = wm + mi * 16 + (lane & 15);
                int col = kk * 16 + ((lane >> 4) << 3);
                uint32_t ad = aBase + buf * GBUF + row * GROW + col * 2;
                ldsm4(ad, a[mi][0], a[mi][1], a[mi][2], a[mi][3]);
            }
            uint32_t b[4][2];
            #pragma unroll
            for (int ng = 0; ng < 2; ng++) {
                int mm = lane >> 3;
                int row = wn + ng * 16 + (mm >> 1) * 8 + (lane & 7);
                int col = kk * 16 + (mm & 1) * 8;
                uint32_t bd = bBase + buf * GBUF + row * GROW + col * 2;
                uint32_t r0, r1, r2, r3;
                ldsm4(bd, r0, r1, r2, r3);
                b[ng * 2][0] = r0; b[ng * 2][1] = r1;
                b[ng * 2 + 1][0] = r2; b[ng * 2 + 1][1] = r3;
            }
            #pragma unroll
            for (int mi = 0; mi < 4; mi++)
                #pragma unroll
                for (int nj = 0; nj < 4; nj++)
                    mma16816(acc[mi][nj], a[mi], b[nj]);
        }
        __syncthreads();
    }

    #pragma unroll
    for (int mi = 0; mi < 4; mi++) {
        int r0 = bm + wm + mi * 16 + (lane >> 2);
        int r1 = r0 + 8;
        #pragma unroll
        for (int nj = 0; nj < 4; nj++) {
            int cb = bn + wn + nj * 8 + (lane & 3) * 2;
            if (cb >= N) continue;
            float* c = acc[mi][nj];
            float b0 = bias[cb], b1 = bias[cb + 1];
            float v00 = c[0] + b0, v01 = c[1] + b1;
            float v10 = c[2] + b0, v11 = c[3] + b1;
            if (EPI == 2) {
                v00 = gelu_f(v00); v01 = gelu_f(v01);
                v10 = gelu_f(v10); v11 = gelu_f(v11);
            }
            if (EPI == 0 || EPI == 2) {
                __nv_bfloat16* Y = (__nv_bfloat16*)Yv;
                *(__nv_bfloat162*)(Y + (size_t)r0 * N + cb) = __floats2bfloat162_rn(v00, v01);
                *(__nv_bfloat162*)(Y + (size_t)r1 * N + cb) = __floats2bfloat162_rn(v10, v11);
            } else if (EPI == 4) {
                if (cb < 384) {
                    float* OFF = (float*)Yv;
                    *(float2*)(OFF + (size_t)r0 * 384 + cb) = make_float2(v00, v01);
                    *(float2*)(OFF + (size_t)r1 * 384 + cb) = make_float2(v10, v11);
                } else if (cb < 576) {
                    float* AWL = (float*)res;
                    *(float2*)(AWL + (size_t)r0 * 192 + cb - 384) = make_float2(v00, v01);
                    *(float2*)(AWL + (size_t)r1 * 192 + cb - 384) = make_float2(v10, v11);
                } else if (cb == 576) {
                    g_ref[(size_t)r0 * 2 + 0] = 1.0f / (1.0f + expf(-v00));
                    g_ref[(size_t)r0 * 2 + 1] = 1.0f / (1.0f + expf(-v01));
                    g_ref[(size_t)r1 * 2 + 0] = 1.0f / (1.0f + expf(-v10));
                    g_ref[(size_t)r1 * 2 + 1] = 1.0f / (1.0f + expf(-v11));
                }
            } else {
                float* Y = (float*)Yv;
                if (EPI == 1) {
                    float2 e0 = *(const float2*)(res + (size_t)r0 * N + cb);
                    float2 e1 = *(const float2*)(res + (size_t)r1 * N + cb);
                    v00 += e0.x; v01 += e0.y; v10 += e1.x; v11 += e1.y;
                }
                *(float2*)(Y + (size_t)r0 * N + cb) = make_float2(v00, v01);
                *(float2*)(Y + (size_t)r1 * N + cb) = make_float2(v10, v11);
            }
        }
    }
}

// ---------------------------------------------------------------------------
// Value-projection GEMM (round-10 proven): BM=64, BN=256, BK=32;
// single A buffer (register-pipelined fp32 LDG) + double B buffer. 46080 B.
// ---------------------------------------------------------------------------
#define VGROW 80
#define VA32 (64 * VGROW)            // 5120
#define VB32 (256 * VGROW)           // 20480
#define VAL_SMEM (VA32 + 2 * VB32)   // 46080

__global__ __launch_bounds__(256, 2) void valgemm_kernel(
    const float* __restrict__ X, const __nv_bfloat16* __restrict__ W,
    const float* __restrict__ bias, __nv_bfloat16* __restrict__ Y)
{
    extern __shared__ __align__(16) uint8_t smem[];
    const int K = 256, N = 256, nch = 8;

    int tid = threadIdx.x, lane = tid & 31, wid = tid >> 5;
    int bm = blockIdx.x * 64;
    int wm = (wid >> 2) * 32, wn = (wid & 3) * 64;
    uint32_t aBase = smem_u32(smem);
    uint32_t bBase = aBase + VA32;

    float acc[2][8][4] = {};
    float4 ra[2];

    auto fetchA = [&](int ch) {
        int k0 = ch << 5;
        #pragma unroll
        for (int t = 0; t < 2; t++) {
            int idx = t * 256 + tid;
            int row = idx >> 3, c4 = idx & 7;
            ra[t] = *(const float4*)(X + (size_t)(bm + row) * K + k0 + c4 * 4);
        }
    };
    auto storeA = [&]() {
        #pragma unroll
        for (int t = 0; t < 2; t++) {
            int idx = t * 256 + tid;
            int row = idx >> 3, c4 = idx & 7;
            __nv_bfloat162 h0 = __floats2bfloat162_rn(ra[t].x, ra[t].y);
            __nv_bfloat162 h1 = __floats2bfloat162_rn(ra[t].z, ra[t].w);
            uint32_t u0 = *(uint32_t*)&h0, u1 = *(uint32_t*)&h1;
            uint32_t d = aBase + row * VGROW + c4 * 8;
            asm volatile("st.shared.v2.b32 [%0], {%1,%2};" :: "r"(d), "r"(u0), "r"(u1));
        }
    };
    auto loadB = [&](int ch, int buf) {
        int k0 = ch << 5;
        #pragma unroll
        for (int t = 0; t < 4; t++) {
            int idx = t * 256 + tid;
            int row = idx >> 2, seg = idx & 3;
            const void* g = W + (size_t)row * K + k0 + seg * 8;
            uint32_t d = bBase + buf * VB32 + row * VGROW + seg * 16;
            asm volatile("cp.async.ca.shared.global [%0], [%1], 16;" :: "r"(d), "l"(g));
        }
    };

    fetchA(0);
    loadB(0, 0);
    asm volatile("cp.async.commit_group;" ::: "memory");
    storeA();
    fetchA(1);

    for (int ch = 0; ch < nch; ch++) {
        int buf = ch & 1;
        if (ch + 1 < nch) {
            loadB(ch + 1, buf ^ 1);
            asm volatile("cp.async.commit_group;" ::: "memory");
            asm volatile("cp.async.wait_group 1;" ::: "memory");
        } else {
            asm volatile("cp.async.wait_group 0;" ::: "memory");
        }
        __syncthreads();

        #pragma unroll
        for (int kk = 0; kk < 2; kk++) {
            uint32_t a[2][4];
            #pragma unroll
            for (int mi = 0; mi < 2; mi++) {
                int row = wm + mi * 16 + (lane & 15);
                int col = kk * 16 + ((lane >> 4) << 3);
                uint32_t ad = aBase + row * VGROW + col * 2;
                ldsm4(ad, a[mi][0], a[mi][1], a[mi][2], a[mi][3]);
            }
            uint32_t b[8][2];
            #pragma unroll
            for (int ng = 0; ng < 4; ng++) {
                int mm = lane >> 3;
                int row = wn + ng * 16 + (mm >> 1) * 8 + (lane & 7);
                int col = kk * 16 + (mm & 1) * 8;
                uint32_t bd = bBase + buf * VB32 + row * VGROW + col * 2;
                uint32_t r0, r1, r2, r3;
                ldsm4(bd, r0, r1, r2, r3);
                b[ng * 2][0] = r0; b[ng * 2][1] = r1;
                b[ng * 2 + 1][0] = r2; b[ng * 2 + 1][1] = r3;
            }
            #pragma unroll
            for (int mi = 0; mi < 2; mi++)
                #pragma unroll
                for (int nj = 0; nj < 8; nj++)
                    mma16816(acc[mi][nj], a[mi], b[nj]);
        }
        __syncthreads();

        if (ch + 1 < nch) {
            storeA();
            if (ch + 2 < nch) fetchA(ch + 2);
        }
    }

    #pragma unroll
    for (int mi = 0; mi < 2; mi++) {
        int r0 = bm + wm + mi * 16 + (lane >> 2);
        int r1 = r0 + 8;
        #pragma unroll
        for (int nj = 0; nj < 8; nj++) {
            int cb = wn + nj * 8 + (lane & 3) * 2;
            float* c = acc[mi][nj];
            float b0 = bias[cb], b1 = bias[cb + 1];
            *(__nv_bfloat162*)(Y + (size_t)r0 * N + cb) =
                __floats2bfloat162_rn(c[0] + b0, c[1] + b1);
            *(__nv_bfloat162*)(Y + (size_t)r1 * N + cb) =
                __floats2bfloat162_rn(c[2] + b0, c[3] + b1);
        }
    }
}

// ---------------------------------------------------------------------------
// Flash self-attention on mma.sync (base-2 online softmax, raw-score max).
// ---------------------------------------------------------------------------
__global__ __launch_bounds__(256) void attn_mma_kernel(
    const __nv_bfloat16* __restrict__ qkv, __nv_bfloat16* __restrict__ out)
{
    const float scale2 = 0.17677669529663687f * 1.4426950408889634f;
    int bh = blockIdx.y;
    int b = bh >> 3, h = bh & 7;
    int q0 = blockIdx.x * 128;
    int tid = threadIdx.x, lane = tid & 31, wid = tid >> 5;

    __shared__ __align__(16) uint8_t sQ[128 * 80];
    __shared__ __align__(16) uint8_t sK[2][64 * 80];
    __shared__ __align__(16) uint8_t sV[2][64 * 80];
    uint32_t qBase = smem_u32(sQ), kBase = smem_u32(sK), vBase = smem_u32(sV);

    #pragma unroll
    for (int t = 0; t < 2; t++) {
        int idx = t * 256 + tid;
        int row = idx >> 2, seg = idx & 3;
        const void* g = qkv + ((size_t)(b * NQ_ + q0 + row)) * 768 + h * 32 + seg * 8;
        asm volatile("cp.async.ca.shared.global [%0], [%1], 16;"
                     :: "r"(qBase + row * 80 + seg * 16), "l"(g));
    }
    auto loadKV = [&](int kb, int buf) {
        int row = tid >> 2, seg = tid & 3;
        size_t rbase = ((size_t)(b * NQ_ + kb * 64 + row)) * 768 + h * 32 + seg * 8;
        asm volatile("cp.async.ca.shared.global [%0], [%1], 16;"
                     :: "r"(kBase + buf * 5120 + row * 80 + seg * 16), "l"(qkv + rbase + 256));
        asm volatile("cp.async.ca.shared.global [%0], [%1], 16;"
                     :: "r"(vBase + buf * 5120 + row * 80 + seg * 16), "l"(qkv + rbase + 512));
    };
    loadKV(0, 0);
    asm volatile("cp.async.commit_group;" ::: "memory");
    loadKV(1, 1);
    asm volatile("cp.async.commit_group;" ::: "memory");
    asm volatile("cp.async.wait_group 1;" ::: "memory");
    __syncthreads();

    uint32_t qa[2][4];
    int wq = wid * 16;
    #pragma unroll
    for (int ks = 0; ks < 2; ks++) {
        int row = wq + (lane & 15);
        int col = ks * 16 + ((lane >> 4) << 3);
        ldsm4(qBase + row * 80 + col * 2, qa[ks][0], qa[ks][1], qa[ks][2], qa[ks][3]);
    }

    float o[4][4] = {};
    float m0 = -1e30f, m1 = -1e30f, l0 = 0.f, l1 = 0.f;
    int g8 = lane >> 3;

    for (int kb = 0; kb < 16; kb++) {
        int buf = kb & 1;

        float s[8][4] = {};
        #pragma unroll
        for (int jp = 0; jp < 4; jp++) {
            #pragma unroll
            for (int ks = 0; ks < 2; ks++) {
                int row = jp * 16 + ((g8 >> 1) << 3) + (lane & 7);
                int col = ks * 16 + ((g8 & 1) << 3);
                uint32_t r0, r1, r2, r3;
                ldsm4(kBase + buf * 5120 + row * 80 + col * 2, r0, r1, r2, r3);
                uint32_t bb0[2] = {r0, r1}, bb1[2] = {r2, r3};
                mma16816(s[jp * 2], qa[ks], bb0);
                mma16816(s[jp * 2 + 1], qa[ks], bb1);
            }
        }

        float mn0 = m0, mn1 = m1;
        #pragma unroll
        for (int j = 0; j < 8; j++) {
            mn0 = fmaxf(mn0, fmaxf(s[j][0], s[j][1]));
            mn1 = fmaxf(mn1, fmaxf(s[j][2], s[j][3]));
        }
        mn0 = fmaxf(mn0, __shfl_xor_sync(0xFFFFFFFFu, mn0, 1));
        mn0 = fmaxf(mn0, __shfl_xor_sync(0xFFFFFFFFu, mn0, 2));
        mn1 = fmaxf(mn1, __shfl_xor_sync(0xFFFFFFFFu, mn1, 1));
        mn1 = fmaxf(mn1, __shfl_xor_sync(0xFFFFFFFFu, mn1, 2));
        float c0 = exp2f((m0 - mn0) * scale2), c1 = exp2f((m1 - mn1) * scale2);
        m0 = mn0; m1 = mn1;
        float nm0 = mn0 * scale2, nm1 = mn1 * scale2;
        l0 *= c0; l1 *= c1;
        #pragma unroll
        for (int j = 0; j < 8; j++) {
            s[j][0] = exp2f(fmaf(s[j][0], scale2, -nm0));
            s[j][1] = exp2f(fmaf(s[j][1], scale2, -nm0));
            s[j][2] = exp2f(fmaf(s[j][2], scale2, -nm1));
            s[j][3] = exp2f(fmaf(s[j][3], scale2, -nm1));
            l0 += s[j][0] + s[j][1];
            l1 += s[j][2] + s[j][3];
        }

        uint32_t pa[4][4];
        #pragma unroll
        for (int kk = 0; kk < 4; kk++) {
            __nv_bfloat162 h0 = __floats2bfloat162_rn(s[2 * kk][0], s[2 * kk][1]);
            __nv_bfloat162 h1 = __floats2bfloat162_rn(s[2 * kk][2], s[2 * kk][3]);
            __nv_bfloat162 h2 = __floats2bfloat162_rn(s[2 * kk + 1][0], s[2 * kk + 1][1]);
            __nv_bfloat162 h3 = __floats2bfloat162_rn(s[2 * kk + 1][2], s[2 * kk + 1][3]);
            pa[kk][0] = *(uint32_t*)&h0; pa[kk][1] = *(uint32_t*)&h1;
            pa[kk][2] = *(uint32_t*)&h2; pa[kk][3] = *(uint32_t*)&h3;
        }

        #pragma unroll
        for (int nd = 0; nd < 4; nd++) {
            o[nd][0] *= c0; o[nd][1] *= c0; o[nd][2] *= c1; o[nd][3] *= c1;
        }

        #pragma unroll
        for (int kk = 0; kk < 4; kk++) {
            #pragma unroll
            for (int np = 0; np < 2; np++) {
                int row = kk * 16 + ((g8 & 1) << 3) + (lane & 7);
                int col = np * 16 + ((g8 >> 1) << 3);
                uint32_t r0, r1, r2, r3;
                ldsm4t(vBase + buf * 5120 + row * 80 + col * 2, r0, r1, r2, r3);
                uint32_t bb0[2] = {r0, r1}, bb1[2] = {r2, r3};
                mma16816(o[np * 2], pa[kk], bb0);
                mma16816(o[np * 2 + 1], pa[kk], bb1);
            }
        }

        __syncthreads();
        if (kb + 2 < 16) {
            loadKV(kb + 2, buf);
            asm volatile("cp.async.commit_group;" ::: "memory");
            asm volatile("cp.async.wait_group 1;" ::: "memory");
            __syncthreads();
        } else if (kb + 1 < 16) {
            asm volatile("cp.async.wait_group 0;" ::: "memory");
            __syncthreads();
        }
    }

    l0 += __shfl_xor_sync(0xFFFFFFFFu, l0, 1);
    l0 += __shfl_xor_sync(0xFFFFFFFFu, l0, 2);
    l1 += __shfl_xor_sync(0xFFFFFFFFu, l1, 1);
    l1 += __shfl_xor_sync(0xFFFFFFFFu, l1, 2);

    float inv0 = 1.f / l0, inv1 = 1.f / l1;
    int r = lane >> 2;
    int cb = (lane & 3) * 2;
    size_t mr0 = (size_t)(b * NQ_ + q0 + wq + r);
    size_t mr1 = mr0 + 8;
    #pragma unroll
    for (int nd = 0; nd < 4; nd++) {
        int col = h * 32 + nd * 8 + cb;
        *(__nv_bfloat162*)(out + mr0 * C_ + col) =
            __floats2bfloat162_rn(o[nd][0] * inv0, o[nd][1] * inv0);
        *(__nv_bfloat162*)(out + mr1 * C_ + col) =
            __floats2bfloat162_rn(o[nd][2] * inv1, o[nd][3] * inv1);
    }
}

// ---------------------------------------------------------------------------
// MS-deformable sampling (bf16 value, bf16 out)
// ---------------------------------------------------------------------------
__global__ __launch_bounds__(256) void deform_kernel(
    const __nv_bfloat16* __restrict__ value, const float* __restrict__ ref,
    const float* __restrict__ off, const float* __restrict__ awl,
    __nv_bfloat16* __restrict__ out)
{
    int gwarp = (blockIdx.x * blockDim.x + threadIdx.x) >> 5;
    int lane = threadIdx.x & 31;
    int m = gwarp >> 3;
    int h = gwarp & 7;
    int b = m >> 10;

    float logit = -1e30f;
    if (lane < 24) logit = awl[(size_t)m * 192 + h * 24 + lane];
    float mx = logit;
    #pragma unroll
    for (int o = 16; o > 0; o >>= 1) mx = fmaxf(mx, __shfl_xor_sync(0xFFFFFFFFu, mx, o));
    float e = (lane < 24) ? __expf(logit - mx) : 0.f;
    float sum = e;
    #pragma unroll
    for (int o = 16; o > 0; o >>= 1) sum += __shfl_xor_sync(0xFFFFFFFFu, sum, o);
    float inv = 1.f / sum;

    float rx = ref[(size_t)m * 2 + 0];
    float ry = ref[(size_t)m * 2 + 1];

    const int HL[3] = {128, 64, 32};
    const int WL[3] = {128, 64, 32};
    const int ST[3] = {0, 16384, 20480};

    float acc = 0.f;
    #pragma unroll
    for (int l = 0; l < 3; l++) {
        int h_l = HL[l], w_l = WL[l];
        const __nv_bfloat16* base = value + ((size_t)b * S_ + ST[l]) * C_ + h * 32 + lane;
        float fw = (float)w_l, fh = (float)h_l;
        #pragma unroll
        for (int p = 0; p < 8; p++) {
            int j = l * 8 + p;
            float aw = __shfl_sync(0xFFFFFFFFu, e, j) * inv;
            size_t ob = (size_t)m * 384 + ((h * 3 + l) * 8 + p) * 2;
            float ox = off[ob + 0];
            float oy = off[ob + 1];
            float locx = rx + ox / fw;
            float locy = ry + oy / fh;
            float gx = locx * fw - 0.5f;
            float gy = locy * fh - 0.5f;
            float x0f = floorf(gx), y0f = floorf(gy);
            float lx = gx - x0f, ly = gy - y0f;
            int x0 = (int)x0f, y0 = (int)y0f;
            int x1 = x0 + 1, y1 = y0 + 1;
            bool vx0 = ((unsigned)x0 < (unsigned)w_l);
            bool vx1 = ((unsigned)x1 < (unsigned)w_l);
            bool vy0 = ((unsigned)y0 < (unsigned)h_l);
            bool vy1 = ((unsigned)y1 < (unsigned)h_l);
            int x0c = min(max(x0, 0), w_l - 1);
            int x1c = min(max(x1, 0), w_l - 1);
            int y0c = min(max(y0, 0), h_l - 1);
            int y1c = min(max(y1, 0), h_l - 1);
            float v00 = 0.f, v01 = 0.f, v10 = 0.f, v11 = 0.f;
            if (vy0) {
                if (vx0) v00 = __bfloat162float(base[(size_t)(y0c * w_l + x0c) * C_]);
                if (vx1) v01 = __bfloat162float(base[(size_t)(y0c * w_l + x1c) * C_]);
            }
            if (vy1) {
                if (vx0) v10 = __bfloat162float(base[(size_t)(y1c * w_l + x0c) * C_]);
                if (vx1) v11 = __bfloat162float(base[(size_t)(y1c * w_l + x1c) * C_]);
            }
            float sres = v00 * ((1.f - lx) * (1.f - ly))
                       + v01 * (lx * (1.f - ly))
                       + v10 * ((1.f - lx) * ly)
                       + v11 * (lx * ly);
            acc += aw * sres;
        }
    }
    out[(size_t)m * C_ + h * 32 + lane] = __float2bfloat16(acc);
}

// ---------------------------------------------------------------------------
// Launch
// ---------------------------------------------------------------------------
extern "C" void kernel_launch(void* const* d_in, const int* in_sizes, int n_in,
                              void* d_out, int out_size)
{
    const float* tgt        = (const float*)d_in[0];
    const float* memory     = (const float*)d_in[1];
    const float* n1_w       = (const float*)d_in[2];
    const float* n1_b       = (const float*)d_in[3];
    const float* attn_in_w  = (const float*)d_in[4];
    const float* attn_in_b  = (const float*)d_in[5];
    const float* attn_out_w = (const float*)d_in[6];
    const float* attn_out_b = (const float*)d_in[7];
    const float* n2_w       = (const float*)d_in[8];
    const float* n2_b       = (const float*)d_in[9];
    const float* ref_w      = (const float*)d_in[10];
    const float* ref_b      = (const float*)d_in[11];
    const float* so_w       = (const float*)d_in[12];
    const float* so_b       = (const float*)d_in[13];
    const float* aw_w       = (const float*)d_in[14];
    const float* aw_b       = (const float*)d_in[15];
    const float* vp_w       = (const float*)d_in[16];
    const float* vp_b       = (const float*)d_in[17];
    const float* op_w       = (const float*)d_in[18];
    const float* op_b       = (const float*)d_in[19];
    const float* n3_w       = (const float*)d_in[20];
    const float* n3_b       = (const float*)d_in[21];
    const float* l1_w       = (const float*)d_in[22];
    const float* l1_b       = (const float*)d_in[23];
    const float* l2_w       = (const float*)d_in[24];
    const float* l2_b       = (const float*)d_in[25];
    float* out = (float*)d_out;

    void* p;
    cudaGetSymbolAddress(&p, g_q1b);    __nv_bfloat16* q1    = (__nv_bfloat16*)p;
    cudaGetSymbolAddress(&p, g_qkvb);   __nv_bfloat16* qkv   = (__nv_bfloat16*)p;
    cudaGetSymbolAddress(&p, g_aob);    __nv_bfloat16* ao    = (__nv_bfloat16*)p;
    cudaGetSymbolAddress(&p, g_tgt1);   float* tgt1          = (float*)p;
    cudaGetSymbolAddress(&p, g_q2b);    __nv_bfloat16* q2    = (__nv_bfloat16*)p;
    cudaGetSymbolAddress(&p, g_valb);   __nv_bfloat16* valb  = (__nv_bfloat16*)p;
    cudaGetSymbolAddress(&p, g_ref);    float* refb          = (float*)p;
    cudaGetSymbolAddress(&p, g_off);    float* offb          = (float*)p;
    cudaGetSymbolAddress(&p, g_awl);    float* awlb          = (float*)p;
    cudaGetSymbolAddress(&p, g_sampb);  __nv_bfloat16* samp  = (__nv_bfloat16*)p;
    cudaGetSymbolAddress(&p, g_tgt2);   float* tgt2          = (float*)p;
    cudaGetSymbolAddress(&p, g_q3b);    __nv_bfloat16* q3    = (__nv_bfloat16*)p;
    cudaGetSymbolAddress(&p, g_ffhb);   __nv_bfloat16* ffh   = (__nv_bfloat16*)p;
    cudaGetSymbolAddress(&p, g_w_qkv);  __nv_bfloat16* wqkv  = (__nv_bfloat16*)p;
    cudaGetSymbolAddress(&p, g_w_ao);   __nv_bfloat16* wao   = (__nv_bfloat16*)p;
    cudaGetSymbolAddress(&p, g_w_vp);   __nv_bfloat16* wvp   = (__nv_bfloat16*)p;
    cudaGetSymbolAddress(&p, g_w_op);   __nv_bfloat16* wop   = (__nv_bfloat16*)p;
    cudaGetSymbolAddress(&p, g_w_soaw); __nv_bfloat16* wsoaw = (__nv_bfloat16*)p;
    cudaGetSymbolAddress(&p, g_b_soaw); float* bsoaw         = (float*)p;
    cudaGetSymbolAddress(&p, g_w_l1);   __nv_bfloat16* wl1   = (__nv_bfloat16*)p;
    cudaGetSymbolAddress(&p, g_w_l2);   __nv_bfloat16* wl2   = (__nv_bfloat16*)p;

    cudaFuncSetAttribute(mmagemm_kernel<0>, cudaFuncAttributeMaxDynamicSharedMemorySize, GEMM_SMEM);
    cudaFuncSetAttribute(mmagemm_kernel<1>, cudaFuncAttributeMaxDynamicSharedMemorySize, GEMM_SMEM);
    cudaFuncSetAttribute(mmagemm_kernel<2>, cudaFuncAttributeMaxDynamicSharedMemorySize, GEMM_SMEM);
    cudaFuncSetAttribute(mmagemm_kernel<4>, cudaFuncAttributeMaxDynamicSharedMemorySize, GEMM_SMEM);
    cudaFuncSetAttribute(valgemm_kernel,    cudaFuncAttributeMaxDynamicSharedMemorySize, VAL_SMEM);

    cvt_weights_kernel<<<(CVT_TOTAL4 + 255) / 256, 256>>>(
        attn_in_w, attn_out_w, vp_w, op_w, so_w, aw_w, ref_w, ref_b,
        l1_w, l2_w, so_b, aw_b,
        wqkv, wao, wvp, wop, wsoaw, bsoaw, wl1, wl2);

    // ---- fork: value projection on side stream ----
    cudaEventRecord(g_evF, 0);
    cudaStreamWaitEvent(g_s2, g_evF, 0);
    valgemm_kernel<<<MV_ROWS / 64, 256, VAL_SMEM, g_s2>>>(memory, wvp, vp_b, valb);
    cudaEventRecord(g_evJ, g_s2);

    // ---- self-attention block ----
    layernorm_kernel<<<M_ROWS / 8, 256>>>(tgt, n1_w, n1_b, q1);
    mmagemm_kernel<0><<<dim3(6, 64), 256, GEMM_SMEM>>>(q1, wqkv, attn_in_b, nullptr,
                                                       qkv, M_ROWS, 768, C_);
    attn_mma_kernel<<<dim3(NQ_ / 128, B_ * H_), 256>>>(qkv, ao);
    mmagemm_kernel<1><<<dim3(2, 64), 256, GEMM_SMEM>>>(ao, wao, attn_out_b, tgt,
                                                       tgt1, M_ROWS, C_, C_);

    // ---- deformable cross-attention block ----
    layernorm_kernel<<<M_ROWS / 8, 256>>>(tgt1, n2_w, n2_b, q2);
    mmagemm_kernel<4><<<dim3(5, 64), 256, GEMM_SMEM>>>(q2, wsoaw, bsoaw,
                                                       awlb, offb, M_ROWS, 640, C_);
    cudaStreamWaitEvent(0, g_evJ, 0);
    deform_kernel<<<(M_ROWS * H_) / 8, 256>>>(valb, refb, offb, awlb, samp);
    mmagemm_kernel<1><<<dim3(2, 64), 256, GEMM_SMEM>>>(samp, wop, op_b, tgt1,
                                                       tgt2, M_ROWS, C_, C_);

    // ---- FFN block ----
    layernorm_kernel<<<M_ROWS / 8, 256>>>(tgt2, n3_w, n3_b, q3);
    mmagemm_kernel<2><<<dim3(8, 64), 256, GEMM_SMEM>>>(q3, wl1, l1_b, nullptr,
                                                       ffh, M_ROWS, FF_, C_);
    mmagemm_kernel<1><<<dim3(2, 64), 256, GEMM_SMEM>>>(ffh, wl2, l2_b, tgt2,
                                                       out, M_ROWS, C_, FF_);
}